// round 4
// baseline (speedup 1.0000x reference)
#include <cuda_runtime.h>
#include <math_constants.h>

#define BB 2
#define HH 256
#define WW 256
#define PTS 64
#define IMP 64
#define NRAYS (BB*HH*WW)          // 131072
#define NEARP 0.1f
#define FARP  2.0f
#define DSTEP ((FARP-NEARP)/63.0f)
#define FOCAL 4.2f

#define OFS_C 0
#define OFS_F (BB*3*HH*WW)        // 393216
#define OFS_D (2*BB*3*HH*WW)      // 786432

// statically initialized; reset by the LAST norm_kernel block each run
__device__ int g_min_bits = 0x7f800000;
__device__ int g_max_bits = 0;
__device__ int g_done     = 0;

__device__ __forceinline__ float tanh_approx(float x) {
    float y;
    asm("tanh.approx.f32 %0, %1;" : "=f"(y) : "f"(x));
    return y;
}

// sigmoid(x) = 0.5*tanh(0.5*x) + 0.5   -> 1 MUFU.TANH + 2 FMA
__device__ __forceinline__ float sigm(float x) {
    return fmaf(tanh_approx(0.5f * x), 0.5f, 0.5f);
}

__global__ __launch_bounds__(128) void render_kernel(
    const float* __restrict__ tm,   // (B,3,4)
    const float* __restrict__ Wq,   // (6,4)
    float* __restrict__ out)
{
    int r = blockIdx.x * blockDim.x + threadIdx.x;
    if (r >= NRAYS) return;
    int b = r >> 16;
    int n = r & 65535;
    int iy = n >> 8;       // image row
    int jx = n & 255;      // image col

    float cx = fmaf((float)jx, -2.0f / 255.0f, 1.0f) * (1.0f / FOCAL);
    float cy = fmaf((float)iy, -2.0f / 255.0f, 1.0f) * (1.0f / FOCAL);

    const float* T = tm + b * 12;
    float dx = __ldg(T + 0) * cx + __ldg(T + 1) * cy + __ldg(T + 2);
    float dy = __ldg(T + 4) * cx + __ldg(T + 5) * cy + __ldg(T + 6);
    float dz = __ldg(T + 8) * cx + __ldg(T + 9) * cy + __ldg(T + 10);
    float ox = __ldg(T + 3), oy = __ldg(T + 7), oz = __ldg(T + 11);

    // feat(depth)[c] = base[c] + depth * kk[c]
    float base[4], kk[4];
#pragma unroll
    for (int c = 0; c < 4; c++) {
        base[c] = ox * __ldg(Wq + 0 * 4 + c) + oy * __ldg(Wq + 1 * 4 + c) + oz * __ldg(Wq + 2 * 4 + c)
                + dx * __ldg(Wq + 3 * 4 + c) + dy * __ldg(Wq + 4 * 4 + c) + dz * __ldg(Wq + 5 * 4 + c);
        kk[c]   = dx * __ldg(Wq + 0 * 4 + c) + dy * __ldg(Wq + 1 * 4 + c) + dz * __ldg(Wq + 2 * 4 + c);
    }

    float  cdf[PTS];   // unnormalized cumsum of (w + 1e-5)
    float  fd[IMP];    // fine (importance) depths, sorted by construction
    float4 sc[PTS];    // cached coarse samples: {op, v0, v1, v2}

    // ---------------- Pass 1: coarse ray march + cdf build + sample cache ----------------
    float absorption = 1.0f;
    float a0 = 0.0f, a1 = 0.0f, a2 = 0.0f;
    float cum = 0.0f;
#pragma unroll 4
    for (int p = 0; p < PTS; p++) {
        float d = NEARP + p * DSTEP;
        float op = sigm(fmaf(d, kk[0], base[0]));
        float v0 = sigm(fmaf(d, kk[1], base[1]));
        float v1 = sigm(fmaf(d, kk[2], base[2]));
        float v2 = sigm(fmaf(d, kk[3], base[3]));
        sc[p] = make_float4(op, v0, v1, v2);
        float w = op * absorption;
        absorption *= (1.0f - op);
        a0 = fmaf(w, v0, a0);
        a1 = fmaf(w, v1, a1);
        a2 = fmaf(w, v2, a2);
        cum += w + 1e-5f;
        cdf[p] = cum;
    }
    out[OFS_C + ((b * 3 + 0) << 16) + n] = a0;
    out[OFS_C + ((b * 3 + 1) << 16) + n] = a1;
    out[OFS_C + ((b * 3 + 2) << 16) + n] = a2;

    float inv_total = __fdividef(1.0f, cum);

    // ---------------- Pass 2: inverse-CDF sampling (streaming searchsorted) ----------------
    {
        int jp = 0;
        float prev_bin = 0.0f;
#pragma unroll 1
        for (int k = 0; k <= IMP; k++) {
            float u = (float)k * (1.0f / 64.0f);
            while (jp < PTS && cdf[jp] * inv_total <= u) jp++;
            int below = (jp - 1 < 0) ? 0 : (jp - 1);
            int above = (jp > PTS - 1) ? (PTS - 1) : jp;
            float c0 = cdf[below] * inv_total;
            float c1 = cdf[above] * inv_total;
            float d0 = NEARP + below * DSTEP;
            float d1 = NEARP + above * DSTEP;
            float dd = c1 - c0;
            float denom = (dd < 1e-8f) ? 1.0f : dd;
            float t = __fdividef(u - c0, denom);
            t = fminf(fmaxf(t, 0.0f), 1.0f);
            float bin = fmaf(t, d1 - d0, d0);
            if (k > 0) fd[k - 1] = 0.5f * (prev_bin + bin);
            prev_bin = bin;
        }
    }

    // ---------------- Pass 3: merged (coarse ∪ fine) ray march ----------------
    // Coarse samples come from the cache (no tanh); only fine points recompute.
    absorption = 1.0f;
    a0 = a1 = a2 = 0.0f;
    float wsum = 0.0f, dsum = 0.0f;
    int ic = 0, jf = 0;
#pragma unroll 1
    for (int m = 0; m < PTS + IMP; m++) {
        float dc = (ic < PTS) ? fmaf((float)ic, DSTEP, NEARP) : CUDART_INF_F;
        float df = (jf < IMP) ? fd[jf] : CUDART_INF_F;
        float d, op, v0, v1, v2;
        if (dc <= df) {                 // stable: coarse first on ties
            float4 s = sc[ic];
            d = dc; op = s.x; v0 = s.y; v1 = s.z; v2 = s.w;
            ic++;
        } else {
            d = df; jf++;
            op = sigm(fmaf(d, kk[0], base[0]));
            v0 = sigm(fmaf(d, kk[1], base[1]));
            v1 = sigm(fmaf(d, kk[2], base[2]));
            v2 = sigm(fmaf(d, kk[3], base[3]));
        }
        float w = op * absorption;
        absorption *= (1.0f - op);
        a0 = fmaf(w, v0, a0);
        a1 = fmaf(w, v1, a1);
        a2 = fmaf(w, v2, a2);
        wsum += w;
        dsum = fmaf(w, d, dsum);
    }
    out[OFS_F + ((b * 3 + 0) << 16) + n] = a0;
    out[OFS_F + ((b * 3 + 1) << 16) + n] = a1;
    out[OFS_F + ((b * 3 + 2) << 16) + n] = a2;

    // ray depth: sum(w*d) + (1 - clip(sum w,0,1)) * max(d_all) [= FAR exactly]
    float f_accum_op = fminf(wsum, 1.0f);
    float rd = dsum + (1.0f - f_accum_op) * FARP;
    out[OFS_D + (b << 16) + n] = rd;

    // global min/max reduction: warp shuffle then int-bit atomics (rd > 0)
    float mn = rd, mx = rd;
#pragma unroll
    for (int o = 16; o > 0; o >>= 1) {
        mn = fminf(mn, __shfl_xor_sync(0xffffffffu, mn, o));
        mx = fmaxf(mx, __shfl_xor_sync(0xffffffffu, mx, o));
    }
    if ((threadIdx.x & 31) == 0) {
        atomicMin(&g_min_bits, __float_as_int(mn));
        atomicMax(&g_max_bits, __float_as_int(mx));
    }
}

__global__ __launch_bounds__(256) void norm_kernel(float* __restrict__ out) {
    // read BEFORE the completion-counter increment below (ordered by __syncthreads)
    float mn = __int_as_float(g_min_bits);
    float mx = __int_as_float(g_max_bits);
    float inv = __fdividef(1.0f, mx - mn);
    int idx = blockIdx.x * blockDim.x + threadIdx.x;
    if (idx < NRAYS) {
        float v = out[OFS_D + idx];
        out[OFS_D + idx] = (v - mn) * inv;
    }
    __syncthreads();
    if (threadIdx.x == 0) {
        int t = atomicAdd(&g_done, 1);
        if (t == (int)gridDim.x - 1) {
            // last block: everyone has read -> reset state for the next replay
            g_done     = 0;
            g_min_bits = 0x7f800000;
            g_max_bits = 0;
            __threadfence();
        }
    }
}

extern "C" void kernel_launch(void* const* d_in, const int* in_sizes, int n_in,
                              void* d_out, int out_size) {
    const float* tm = (const float*)d_in[0];   // transform_matrix (2,3,4)
    const float* Wq = (const float*)d_in[1];   // W_query (6,4)
    float* out = (float*)d_out;

    render_kernel<<<NRAYS / 128, 128>>>(tm, Wq, out);
    norm_kernel<<<(NRAYS + 255) / 256, 256>>>(out);
}

// round 5
// speedup vs baseline: 2.0691x; 2.0691x over previous
#include <cuda_runtime.h>
#include <math_constants.h>

#define BB 2
#define HH 256
#define WW 256
#define PTS 64
#define IMP 64
#define NRAYS (BB*HH*WW)          // 131072
#define NEARP 0.1f
#define FARP  2.0f
#define DSTEP ((FARP-NEARP)/63.0f)
#define FOCAL 4.2f

#define OFS_C 0
#define OFS_F (BB*3*HH*WW)        // 393216
#define OFS_D (2*BB*3*HH*WW)      // 786432

// statically initialized; reset by the LAST norm_kernel block each run
__device__ int g_min_bits = 0x7f800000;
__device__ int g_max_bits = 0;
__device__ int g_done     = 0;

__device__ __forceinline__ float tanh_approx(float x) {
    float y;
    asm("tanh.approx.f32 %0, %1;" : "=f"(y) : "f"(x));
    return y;
}

// sigmoid(x) = 0.5*tanh(0.5*x) + 0.5   -> 1 MUFU.TANH + 2 FMA
__device__ __forceinline__ float sigm(float x) {
    return fmaf(tanh_approx(0.5f * x), 0.5f, 0.5f);
}

__global__ __launch_bounds__(128) void render_kernel(
    const float* __restrict__ tm,   // (B,3,4)
    const float* __restrict__ Wq,   // (6,4)
    float* __restrict__ out)
{
    int r = blockIdx.x * blockDim.x + threadIdx.x;
    if (r >= NRAYS) return;
    int b = r >> 16;
    int n = r & 65535;
    int iy = n >> 8;       // image row
    int jx = n & 255;      // image col

    float cx = fmaf((float)jx, -2.0f / 255.0f, 1.0f) * (1.0f / FOCAL);
    float cy = fmaf((float)iy, -2.0f / 255.0f, 1.0f) * (1.0f / FOCAL);

    const float* T = tm + b * 12;
    float dx = __ldg(T + 0) * cx + __ldg(T + 1) * cy + __ldg(T + 2);
    float dy = __ldg(T + 4) * cx + __ldg(T + 5) * cy + __ldg(T + 6);
    float dz = __ldg(T + 8) * cx + __ldg(T + 9) * cy + __ldg(T + 10);
    float ox = __ldg(T + 3), oy = __ldg(T + 7), oz = __ldg(T + 11);

    // feat(depth)[c] = base[c] + depth * kk[c]
    float base[4], kk[4];
#pragma unroll
    for (int c = 0; c < 4; c++) {
        base[c] = ox * __ldg(Wq + 0 * 4 + c) + oy * __ldg(Wq + 1 * 4 + c) + oz * __ldg(Wq + 2 * 4 + c)
                + dx * __ldg(Wq + 3 * 4 + c) + dy * __ldg(Wq + 4 * 4 + c) + dz * __ldg(Wq + 5 * 4 + c);
        kk[c]   = dx * __ldg(Wq + 0 * 4 + c) + dy * __ldg(Wq + 1 * 4 + c) + dz * __ldg(Wq + 2 * 4 + c);
    }

    float cdf[PTS];   // unnormalized cumsum of (w + 1e-5)
    float fd[IMP];    // fine (importance) depths, sorted by construction

    // ---------------- Pass 1: coarse ray march + cdf build ----------------
    float absorption = 1.0f;
    float a0 = 0.0f, a1 = 0.0f, a2 = 0.0f;
    float cum = 0.0f;
#pragma unroll 4
    for (int p = 0; p < PTS; p++) {
        float d = NEARP + p * DSTEP;
        float op = sigm(fmaf(d, kk[0], base[0]));
        float v0 = sigm(fmaf(d, kk[1], base[1]));
        float v1 = sigm(fmaf(d, kk[2], base[2]));
        float v2 = sigm(fmaf(d, kk[3], base[3]));
        float w = op * absorption;
        absorption *= (1.0f - op);
        a0 = fmaf(w, v0, a0);
        a1 = fmaf(w, v1, a1);
        a2 = fmaf(w, v2, a2);
        cum += w + 1e-5f;
        cdf[p] = cum;
    }
    out[OFS_C + ((b * 3 + 0) << 16) + n] = a0;
    out[OFS_C + ((b * 3 + 1) << 16) + n] = a1;
    out[OFS_C + ((b * 3 + 2) << 16) + n] = a2;

    float inv_total = __fdividef(1.0f, cum);

    // ---------------- Pass 2: inverse-CDF sampling (streaming searchsorted) ----------------
    {
        int jp = 0;
        float prev_bin = 0.0f;
#pragma unroll 1
        for (int k = 0; k <= IMP; k++) {
            float u = (float)k * (1.0f / 64.0f);
            while (jp < PTS && cdf[jp] * inv_total <= u) jp++;
            int below = (jp - 1 < 0) ? 0 : (jp - 1);
            int above = (jp > PTS - 1) ? (PTS - 1) : jp;
            float c0 = cdf[below] * inv_total;
            float c1 = cdf[above] * inv_total;
            float d0 = NEARP + below * DSTEP;
            float d1 = NEARP + above * DSTEP;
            float dd = c1 - c0;
            float denom = (dd < 1e-8f) ? 1.0f : dd;
            float t = __fdividef(u - c0, denom);
            t = fminf(fmaxf(t, 0.0f), 1.0f);
            float bin = fmaf(t, d1 - d0, d0);
            if (k > 0) fd[k - 1] = 0.5f * (prev_bin + bin);
            prev_bin = bin;
        }
    }

    // ---------------- Pass 3: merged (coarse ∪ fine) ray march ----------------
    // Recompute all sigmoids (MUFU is cheaper than per-thread local-array traffic).
    absorption = 1.0f;
    a0 = a1 = a2 = 0.0f;
    float wsum = 0.0f, dsum = 0.0f;
    int ic = 0, jf = 0;
#pragma unroll 1
    for (int m = 0; m < PTS + IMP; m++) {
        float dc = (ic < PTS) ? fmaf((float)ic, DSTEP, NEARP) : CUDART_INF_F;
        float df = (jf < IMP) ? fd[jf] : CUDART_INF_F;
        float d;
        if (dc <= df) { d = dc; ic++; }   // stable: coarse first on ties (values identical anyway)
        else          { d = df; jf++; }
        float op = sigm(fmaf(d, kk[0], base[0]));
        float v0 = sigm(fmaf(d, kk[1], base[1]));
        float v1 = sigm(fmaf(d, kk[2], base[2]));
        float v2 = sigm(fmaf(d, kk[3], base[3]));
        float w = op * absorption;
        absorption *= (1.0f - op);
        a0 = fmaf(w, v0, a0);
        a1 = fmaf(w, v1, a1);
        a2 = fmaf(w, v2, a2);
        wsum += w;
        dsum = fmaf(w, d, dsum);
    }
    out[OFS_F + ((b * 3 + 0) << 16) + n] = a0;
    out[OFS_F + ((b * 3 + 1) << 16) + n] = a1;
    out[OFS_F + ((b * 3 + 2) << 16) + n] = a2;

    // ray depth: sum(w*d) + (1 - clip(sum w,0,1)) * max(d_all) [= FAR exactly]
    float f_accum_op = fminf(wsum, 1.0f);
    float rd = dsum + (1.0f - f_accum_op) * FARP;
    out[OFS_D + (b << 16) + n] = rd;

    // global min/max reduction: warp shuffle then int-bit atomics (rd > 0)
    float mn = rd, mx = rd;
#pragma unroll
    for (int o = 16; o > 0; o >>= 1) {
        mn = fminf(mn, __shfl_xor_sync(0xffffffffu, mn, o));
        mx = fmaxf(mx, __shfl_xor_sync(0xffffffffu, mx, o));
    }
    if ((threadIdx.x & 31) == 0) {
        atomicMin(&g_min_bits, __float_as_int(mn));
        atomicMax(&g_max_bits, __float_as_int(mx));
    }
}

// 1MB of depths: float4 + 2 elements/thread for MLP=2, fewer latency-bound threads.
#define NORM_THREADS 256
#define NORM_VEC (NRAYS / 4)              // 32768 float4
#define NORM_BLOCKS (NORM_VEC / (NORM_THREADS * 2))   // 64 blocks, 2 float4/thread

__global__ __launch_bounds__(NORM_THREADS) void norm_kernel(float* __restrict__ out) {
    float mn = __int_as_float(g_min_bits);
    float mx = __int_as_float(g_max_bits);
    float inv = __fdividef(1.0f, mx - mn);

    float4* d = (float4*)(out + OFS_D);
    int i0 = blockIdx.x * (NORM_THREADS * 2) + threadIdx.x;
    float4 v0 = d[i0];
    float4 v1 = d[i0 + NORM_THREADS];
    v0.x = (v0.x - mn) * inv;  v0.y = (v0.y - mn) * inv;
    v0.z = (v0.z - mn) * inv;  v0.w = (v0.w - mn) * inv;
    v1.x = (v1.x - mn) * inv;  v1.y = (v1.y - mn) * inv;
    v1.z = (v1.z - mn) * inv;  v1.w = (v1.w - mn) * inv;
    d[i0] = v0;
    d[i0 + NORM_THREADS] = v1;

    __syncthreads();
    if (threadIdx.x == 0) {
        int t = atomicAdd(&g_done, 1);
        if (t == (int)gridDim.x - 1) {
            // last block: all blocks have read min/max -> reset for next replay
            g_done     = 0;
            g_min_bits = 0x7f800000;
            g_max_bits = 0;
            __threadfence();
        }
    }
}

extern "C" void kernel_launch(void* const* d_in, const int* in_sizes, int n_in,
                              void* d_out, int out_size) {
    const float* tm = (const float*)d_in[0];   // transform_matrix (2,3,4)
    const float* Wq = (const float*)d_in[1];   // W_query (6,4)
    float* out = (float*)d_out;

    render_kernel<<<NRAYS / 128, 128>>>(tm, Wq, out);
    norm_kernel<<<NORM_BLOCKS, NORM_THREADS>>>(out);
}

// round 6
// speedup vs baseline: 2.1296x; 1.0292x over previous
#include <cuda_runtime.h>
#include <math_constants.h>

#define BB 2
#define HH 256
#define WW 256
#define PTS 64
#define IMP 64
#define NRAYS (BB*HH*WW)          // 131072
#define NEARP 0.1f
#define FARP  2.0f
#define DSTEP ((FARP-NEARP)/63.0f)
#define FOCAL 4.2f

#define OFS_C 0
#define OFS_F (BB*3*HH*WW)        // 393216
#define OFS_D (2*BB*3*HH*WW)      // 786432

#define NBLOCKS (NRAYS / 128)     // 1024

// statically initialized; reset by the LAST block each run (graph-replay safe)
__device__ int g_min_bits = 0x7f800000;
__device__ int g_max_bits = 0;
__device__ int g_arrive   = 0;
__device__ int g_release  = 0;
__device__ int g_done     = 0;

__device__ __forceinline__ float tanh_approx(float x) {
    float y;
    asm("tanh.approx.f32 %0, %1;" : "=f"(y) : "f"(x));
    return y;
}

// caller pre-halves the argument: sigmoid(2x') = 0.5*tanh(x') + 0.5
__device__ __forceinline__ float sigm_h(float xh) {
    return fmaf(tanh_approx(xh), 0.5f, 0.5f);
}

// __launch_bounds__(128, 7): 7 blocks/SM * 148 SMs = 1036 >= 1024 blocks
// -> entire grid co-resident in wave 1 -> grid-wide spin barrier is safe.
__global__ void __launch_bounds__(128, 7) render_kernel(
    const float* __restrict__ tm,   // (B,3,4)
    const float* __restrict__ Wq,   // (6,4)
    float* __restrict__ out)
{
    __shared__ float s_mn, s_mx;

    int r = blockIdx.x * blockDim.x + threadIdx.x;
    int b = r >> 16;
    int n = r & 65535;
    int iy = n >> 8;       // image row
    int jx = n & 255;      // image col

    float cx = fmaf((float)jx, -2.0f / 255.0f, 1.0f) * (1.0f / FOCAL);
    float cy = fmaf((float)iy, -2.0f / 255.0f, 1.0f) * (1.0f / FOCAL);

    const float* T = tm + b * 12;
    float dx = __ldg(T + 0) * cx + __ldg(T + 1) * cy + __ldg(T + 2);
    float dy = __ldg(T + 4) * cx + __ldg(T + 5) * cy + __ldg(T + 6);
    float dz = __ldg(T + 8) * cx + __ldg(T + 9) * cy + __ldg(T + 10);
    float ox = __ldg(T + 3), oy = __ldg(T + 7), oz = __ldg(T + 11);

    // 0.5 * feat(depth)[c] = base[c] + depth * kk[c]   (0.5 folded in for tanh)
    float base[4], kk[4];
#pragma unroll
    for (int c = 0; c < 4; c++) {
        base[c] = 0.5f * (ox * __ldg(Wq + 0 * 4 + c) + oy * __ldg(Wq + 1 * 4 + c) + oz * __ldg(Wq + 2 * 4 + c)
                        + dx * __ldg(Wq + 3 * 4 + c) + dy * __ldg(Wq + 4 * 4 + c) + dz * __ldg(Wq + 5 * 4 + c));
        kk[c]   = 0.5f * (dx * __ldg(Wq + 0 * 4 + c) + dy * __ldg(Wq + 1 * 4 + c) + dz * __ldg(Wq + 2 * 4 + c));
    }

    float cdf[PTS];   // unnormalized cumsum of (w + 1e-5)
    float fd[IMP];    // fine (importance) depths, sorted by construction

    // ---------------- Pass 1: coarse ray march + cdf build ----------------
    float absorption = 1.0f;
    float a0 = 0.0f, a1 = 0.0f, a2 = 0.0f;
    float cum = 0.0f;
#pragma unroll 4
    for (int p = 0; p < PTS; p++) {
        float d = NEARP + p * DSTEP;
        float op = sigm_h(fmaf(d, kk[0], base[0]));
        float v0 = sigm_h(fmaf(d, kk[1], base[1]));
        float v1 = sigm_h(fmaf(d, kk[2], base[2]));
        float v2 = sigm_h(fmaf(d, kk[3], base[3]));
        float w = op * absorption;
        absorption *= (1.0f - op);
        a0 = fmaf(w, v0, a0);
        a1 = fmaf(w, v1, a1);
        a2 = fmaf(w, v2, a2);
        cum += w + 1e-5f;
        cdf[p] = cum;
    }
    out[OFS_C + ((b * 3 + 0) << 16) + n] = a0;
    out[OFS_C + ((b * 3 + 1) << 16) + n] = a1;
    out[OFS_C + ((b * 3 + 2) << 16) + n] = a2;

    float inv_total = __fdividef(1.0f, cum);

    // ---------------- Pass 2: inverse-CDF sampling (streaming searchsorted) ----------------
    {
        int jp = 0;
        float prev_bin = 0.0f;
#pragma unroll 1
        for (int k = 0; k <= IMP; k++) {
            float u = (float)k * (1.0f / 64.0f);
            while (jp < PTS && cdf[jp] * inv_total <= u) jp++;
            int below = (jp - 1 < 0) ? 0 : (jp - 1);
            int above = (jp > PTS - 1) ? (PTS - 1) : jp;
            float c0 = cdf[below] * inv_total;
            float c1 = cdf[above] * inv_total;
            float d0 = NEARP + below * DSTEP;
            float d1 = NEARP + above * DSTEP;
            float dd = c1 - c0;
            float denom = (dd < 1e-8f) ? 1.0f : dd;
            float t = __fdividef(u - c0, denom);
            t = fminf(fmaxf(t, 0.0f), 1.0f);
            float bin = fmaf(t, d1 - d0, d0);
            if (k > 0) fd[k - 1] = 0.5f * (prev_bin + bin);
            prev_bin = bin;
        }
    }

    // ---------------- Pass 3: merged (coarse ∪ fine) ray march ----------------
    absorption = 1.0f;
    a0 = a1 = a2 = 0.0f;
    float wsum = 0.0f, dsum = 0.0f;
    int ic = 0, jf = 0;
#pragma unroll 1
    for (int m = 0; m < PTS + IMP; m++) {
        float dc = (ic < PTS) ? fmaf((float)ic, DSTEP, NEARP) : CUDART_INF_F;
        float df = (jf < IMP) ? fd[jf] : CUDART_INF_F;
        float d;
        if (dc <= df) { d = dc; ic++; }   // stable: coarse first on ties (values identical anyway)
        else          { d = df; jf++; }
        float op = sigm_h(fmaf(d, kk[0], base[0]));
        float v0 = sigm_h(fmaf(d, kk[1], base[1]));
        float v1 = sigm_h(fmaf(d, kk[2], base[2]));
        float v2 = sigm_h(fmaf(d, kk[3], base[3]));
        float w = op * absorption;
        absorption *= (1.0f - op);
        a0 = fmaf(w, v0, a0);
        a1 = fmaf(w, v1, a1);
        a2 = fmaf(w, v2, a2);
        wsum += w;
        dsum = fmaf(w, d, dsum);
    }
    out[OFS_F + ((b * 3 + 0) << 16) + n] = a0;
    out[OFS_F + ((b * 3 + 1) << 16) + n] = a1;
    out[OFS_F + ((b * 3 + 2) << 16) + n] = a2;

    // ray depth: sum(w*d) + (1 - clip(sum w,0,1)) * max(d_all) [= FAR exactly]
    float f_accum_op = fminf(wsum, 1.0f);
    float rd = dsum + (1.0f - f_accum_op) * FARP;

    // ---------------- global min/max + grid-wide barrier + normalize ----------------
    float mn = rd, mx = rd;
#pragma unroll
    for (int o = 16; o > 0; o >>= 1) {
        mn = fminf(mn, __shfl_xor_sync(0xffffffffu, mn, o));
        mx = fmaxf(mx, __shfl_xor_sync(0xffffffffu, mx, o));
    }
    if ((threadIdx.x & 31) == 0) {
        atomicMin(&g_min_bits, __float_as_int(mn));   // rd > 0: int order == float order
        atomicMax(&g_max_bits, __float_as_int(mx));
    }
    __syncthreads();

    // grid-wide barrier: whole grid is resident (launch_bounds guarantees it)
    if (threadIdx.x == 0) {
        __threadfence();
        int t = atomicAdd(&g_arrive, 1);
        if (t == NBLOCKS - 1) {
            g_arrive = 0;
            __threadfence();
            atomicExch(&g_release, 1);
        } else {
            while (atomicAdd(&g_release, 0) == 0) { __nanosleep(64); }
        }
        // all writers have arrived -> L2 holds final min/max; bypass L1
        s_mn = __int_as_float(__ldcg(&g_min_bits));
        s_mx = __int_as_float(__ldcg(&g_max_bits));
    }
    __syncthreads();

    float inv = __fdividef(1.0f, s_mx - s_mn);
    out[OFS_D + (b << 16) + n] = (rd - s_mn) * inv;

    // reset state for the next graph replay (after every block has read min/max)
    __syncthreads();
    if (threadIdx.x == 0) {
        int t = atomicAdd(&g_done, 1);
        if (t == NBLOCKS - 1) {
            g_done     = 0;
            g_release  = 0;
            g_min_bits = 0x7f800000;
            g_max_bits = 0;
            __threadfence();
        }
    }
}

extern "C" void kernel_launch(void* const* d_in, const int* in_sizes, int n_in,
                              void* d_out, int out_size) {
    const float* tm = (const float*)d_in[0];   // transform_matrix (2,3,4)
    const float* Wq = (const float*)d_in[1];   // W_query (6,4)
    float* out = (float*)d_out;

    render_kernel<<<NBLOCKS, 128>>>(tm, Wq, out);
}

// round 7
// speedup vs baseline: 2.4936x; 1.1709x over previous
#include <cuda_runtime.h>
#include <math_constants.h>

#define BB 2
#define HH 256
#define WW 256
#define PTS 64
#define IMP 64
#define NRAYS (BB*HH*WW)          // 131072
#define NEARP 0.1f
#define FARP  2.0f
#define DSTEP ((FARP-NEARP)/63.0f)
#define FOCAL 4.2f

#define OFS_C 0
#define OFS_F (BB*3*HH*WW)        // 393216
#define OFS_D (2*BB*3*HH*WW)      // 786432

#define NBLOCKS (NRAYS / 128)     // 1024

// statically initialized; reset by the LAST block each run (graph-replay safe)
__device__ int g_min_bits = 0x7f800000;
__device__ int g_max_bits = 0;
__device__ int g_arrive   = 0;
__device__ int g_release  = 0;
__device__ int g_done     = 0;

__device__ __forceinline__ float tanh_approx(float x) {
    float y;
    asm("tanh.approx.f32 %0, %1;" : "=f"(y) : "f"(x));
    return y;
}

// caller pre-halves the argument: sigmoid(2x') = 0.5*tanh(x') + 0.5
__device__ __forceinline__ float sigm_h(float xh) {
    return fmaf(tanh_approx(xh), 0.5f, 0.5f);
}

// __launch_bounds__(128, 7): 7 blocks/SM * 148 SMs = 1036 >= 1024 blocks
// -> entire grid co-resident in wave 1 -> grid-wide spin barrier is safe.
__global__ void __launch_bounds__(128, 7) render_kernel(
    const float* __restrict__ tm,   // (B,3,4)
    const float* __restrict__ Wq,   // (6,4)
    float* __restrict__ out)
{
    __shared__ float s_mn, s_mx;

    int r = blockIdx.x * blockDim.x + threadIdx.x;
    int b = r >> 16;
    int n = r & 65535;
    int iy = n >> 8;       // image row
    int jx = n & 255;      // image col

    float cx = fmaf((float)jx, -2.0f / 255.0f, 1.0f) * (1.0f / FOCAL);
    float cy = fmaf((float)iy, -2.0f / 255.0f, 1.0f) * (1.0f / FOCAL);

    const float* T = tm + b * 12;
    float dx = __ldg(T + 0) * cx + __ldg(T + 1) * cy + __ldg(T + 2);
    float dy = __ldg(T + 4) * cx + __ldg(T + 5) * cy + __ldg(T + 6);
    float dz = __ldg(T + 8) * cx + __ldg(T + 9) * cy + __ldg(T + 10);
    float ox = __ldg(T + 3), oy = __ldg(T + 7), oz = __ldg(T + 11);

    // 0.5 * feat(depth)[c] = base[c] + depth * kk[c]   (0.5 folded in for tanh)
    float base[4], kk[4];
#pragma unroll
    for (int c = 0; c < 4; c++) {
        base[c] = 0.5f * (ox * __ldg(Wq + 0 * 4 + c) + oy * __ldg(Wq + 1 * 4 + c) + oz * __ldg(Wq + 2 * 4 + c)
                        + dx * __ldg(Wq + 3 * 4 + c) + dy * __ldg(Wq + 4 * 4 + c) + dz * __ldg(Wq + 5 * 4 + c));
        kk[c]   = 0.5f * (dx * __ldg(Wq + 0 * 4 + c) + dy * __ldg(Wq + 1 * 4 + c) + dz * __ldg(Wq + 2 * 4 + c));
    }

    float cdf[PTS];   // unnormalized cumsum of (w + 1e-5); ONLY per-thread array left

    // ---------------- Pass 1: coarse ray march + cdf build ----------------
    float absorption = 1.0f;
    float a0 = 0.0f, a1 = 0.0f, a2 = 0.0f;
    float cum = 0.0f;
#pragma unroll 4
    for (int p = 0; p < PTS; p++) {
        float d = NEARP + p * DSTEP;
        float op = sigm_h(fmaf(d, kk[0], base[0]));
        float v0 = sigm_h(fmaf(d, kk[1], base[1]));
        float v1 = sigm_h(fmaf(d, kk[2], base[2]));
        float v2 = sigm_h(fmaf(d, kk[3], base[3]));
        float w = op * absorption;
        absorption *= (1.0f - op);
        a0 = fmaf(w, v0, a0);
        a1 = fmaf(w, v1, a1);
        a2 = fmaf(w, v2, a2);
        cum += w + 1e-5f;
        cdf[p] = cum;
    }
    out[OFS_C + ((b * 3 + 0) << 16) + n] = a0;
    out[OFS_C + ((b * 3 + 1) << 16) + n] = a1;
    out[OFS_C + ((b * 3 + 2) << 16) + n] = a2;

    float inv_total = __fdividef(1.0f, cum);

    // ---------------- Fused pass 2+3: streaming CDF inversion inside the merge ----------------
    // Generator state: register window over normalized cdf (jp monotone -> sequential LDL only).
    int   jp    = 0;
    float c_jm1 = 0.0f,  d_jm1 = NEARP;            // cdf_n[jp-1], depth[jp-1] (valid once jp>=1)
    float c_j   = cdf[0] * inv_total, d_j = NEARP; // cdf_n[jp],   depth[jp]
    float u     = 0.0f;                            // k/64, exact under incremental FADD

    // generate one sample-cdf bin at current u (advances window), then caller bumps u
    auto gen_bin = [&]() -> float {
        while (jp < PTS && c_j <= u) {
            jp++;
            c_jm1 = c_j;  d_jm1 = d_j;
            if (jp < PTS) { c_j = cdf[jp] * inv_total; d_j += DSTEP; }
            else          { c_j = CUDART_INF_F; }
        }
        float c0 = (jp == 0)   ? c_j   : c_jm1;    // cdf_n[clamp(jp-1,0,63)]
        float d0 = (jp == 0)   ? d_j   : d_jm1;
        float c1 = (jp < PTS)  ? c_j   : c_jm1;    // cdf_n[clamp(jp,0,63)]
        float d1 = (jp < PTS)  ? d_j   : d_jm1;
        float dd = c1 - c0;
        float denom = (dd < 1e-8f) ? 1.0f : dd;
        float t = __fdividef(u - c0, denom);
        t = fminf(fmaxf(t, 0.0f), 1.0f);
        return fmaf(t, d1 - d0, d0);
    };

    // prime: bin_0 and bin_1 -> first fine depth
    float prev_bin = gen_bin();  u += (1.0f / 64.0f);   // bin_0 (== NEARP)
    float bin      = gen_bin();  u += (1.0f / 64.0f);   // bin_1
    float df = 0.5f * (prev_bin + bin);
    prev_bin = bin;
    int kf = 2;        // next bin index to generate
    int jf = 0;        // fine points consumed
    int ic = 0;        // coarse points consumed
    float dc = NEARP;  // next coarse depth (incremental)

    absorption = 1.0f;
    a0 = a1 = a2 = 0.0f;
    float wsum = 0.0f, dsum = 0.0f;
#pragma unroll 1
    for (int m = 0; m < PTS + IMP; m++) {
        bool take_c = (ic < PTS) && (dc <= df);    // df==+inf once fine exhausted
        float d = take_c ? dc : df;
        float op = sigm_h(fmaf(d, kk[0], base[0]));
        float v0 = sigm_h(fmaf(d, kk[1], base[1]));
        float v1 = sigm_h(fmaf(d, kk[2], base[2]));
        float v2 = sigm_h(fmaf(d, kk[3], base[3]));
        float w = op * absorption;
        absorption *= (1.0f - op);
        a0 = fmaf(w, v0, a0);
        a1 = fmaf(w, v1, a1);
        a2 = fmaf(w, v2, a2);
        wsum += w;
        dsum = fmaf(w, d, dsum);
        if (take_c) {
            ic++; dc += DSTEP;
        } else {
            jf++;
            if (kf <= IMP) {
                bin = gen_bin();  u += (1.0f / 64.0f);
                df = 0.5f * (prev_bin + bin);
                prev_bin = bin;
                kf++;
            } else {
                df = CUDART_INF_F;
            }
        }
    }
    out[OFS_F + ((b * 3 + 0) << 16) + n] = a0;
    out[OFS_F + ((b * 3 + 1) << 16) + n] = a1;
    out[OFS_F + ((b * 3 + 2) << 16) + n] = a2;

    // ray depth: sum(w*d) + (1 - clip(sum w,0,1)) * max(d_all) [= FAR exactly]
    float f_accum_op = fminf(wsum, 1.0f);
    float rd = dsum + (1.0f - f_accum_op) * FARP;

    // ---------------- global min/max + grid-wide barrier + normalize ----------------
    float mn = rd, mx = rd;
#pragma unroll
    for (int o = 16; o > 0; o >>= 1) {
        mn = fminf(mn, __shfl_xor_sync(0xffffffffu, mn, o));
        mx = fmaxf(mx, __shfl_xor_sync(0xffffffffu, mx, o));
    }
    if ((threadIdx.x & 31) == 0) {
        atomicMin(&g_min_bits, __float_as_int(mn));   // rd > 0: int order == float order
        atomicMax(&g_max_bits, __float_as_int(mx));
    }
    __syncthreads();

    // grid-wide barrier: whole grid is resident (launch_bounds guarantees it)
    if (threadIdx.x == 0) {
        __threadfence();
        int t = atomicAdd(&g_arrive, 1);
        if (t == NBLOCKS - 1) {
            g_arrive = 0;
            __threadfence();
            atomicExch(&g_release, 1);
        } else {
            while (atomicAdd(&g_release, 0) == 0) { __nanosleep(64); }
        }
        s_mn = __int_as_float(__ldcg(&g_min_bits));
        s_mx = __int_as_float(__ldcg(&g_max_bits));
    }
    __syncthreads();

    float inv = __fdividef(1.0f, s_mx - s_mn);
    out[OFS_D + (b << 16) + n] = (rd - s_mn) * inv;

    // reset state for the next graph replay (after every block has read min/max)
    __syncthreads();
    if (threadIdx.x == 0) {
        int t = atomicAdd(&g_done, 1);
        if (t == NBLOCKS - 1) {
            g_done     = 0;
            g_release  = 0;
            g_min_bits = 0x7f800000;
            g_max_bits = 0;
            __threadfence();
        }
    }
}

extern "C" void kernel_launch(void* const* d_in, const int* in_sizes, int n_in,
                              void* d_out, int out_size) {
    const float* tm = (const float*)d_in[0];   // transform_matrix (2,3,4)
    const float* Wq = (const float*)d_in[1];   // W_query (6,4)
    float* out = (float*)d_out;

    render_kernel<<<NBLOCKS, 128>>>(tm, Wq, out);
}

// round 8
// speedup vs baseline: 2.8154x; 1.1291x over previous
#include <cuda_runtime.h>
#include <math_constants.h>

#define BB 2
#define HH 256
#define WW 256
#define PTS 64
#define IMP 64
#define NRAYS (BB*HH*WW)          // 131072
#define NEARP 0.1f
#define FARP  2.0f
#define DSTEP ((FARP-NEARP)/63.0f)
#define FOCAL 4.2f

#define OFS_C 0
#define OFS_F (BB*3*HH*WW)        // 393216
#define OFS_D (2*BB*3*HH*WW)      // 786432

#define NBLOCKS (NRAYS / 128)     // 1024
#define EPS_ABS 1e-8f             // transmittance cutoff; residual contributions < 64*1e-8

// statically initialized; reset by the LAST block each run (graph-replay safe)
__device__ int g_min_bits = 0x7f800000;
__device__ int g_max_bits = 0;
__device__ int g_arrive   = 0;
__device__ int g_release  = 0;
__device__ int g_done     = 0;

__device__ __forceinline__ float tanh_approx(float x) {
    float y;
    asm("tanh.approx.f32 %0, %1;" : "=f"(y) : "f"(x));
    return y;
}

// caller pre-halves the argument: sigmoid(2x') = 0.5*tanh(x') + 0.5
__device__ __forceinline__ float sigm_h(float xh) {
    return fmaf(tanh_approx(xh), 0.5f, 0.5f);
}

// __launch_bounds__(128, 7): 7 blocks/SM * 148 SMs = 1036 >= 1024 blocks
// -> entire grid co-resident in wave 1 -> grid-wide spin barrier is safe.
__global__ void __launch_bounds__(128, 7) render_kernel(
    const float* __restrict__ tm,   // (B,3,4)
    const float* __restrict__ Wq,   // (6,4)
    float* __restrict__ out)
{
    __shared__ float s_mn, s_mx;

    int r = blockIdx.x * blockDim.x + threadIdx.x;   // grid covers rays exactly; all lanes active
    int b = r >> 16;
    int n = r & 65535;
    int iy = n >> 8;       // image row
    int jx = n & 255;      // image col

    float cx = fmaf((float)jx, -2.0f / 255.0f, 1.0f) * (1.0f / FOCAL);
    float cy = fmaf((float)iy, -2.0f / 255.0f, 1.0f) * (1.0f / FOCAL);

    const float* T = tm + b * 12;
    float dx = __ldg(T + 0) * cx + __ldg(T + 1) * cy + __ldg(T + 2);
    float dy = __ldg(T + 4) * cx + __ldg(T + 5) * cy + __ldg(T + 6);
    float dz = __ldg(T + 8) * cx + __ldg(T + 9) * cy + __ldg(T + 10);
    float ox = __ldg(T + 3), oy = __ldg(T + 7), oz = __ldg(T + 11);

    // 0.5 * feat(depth)[c] = base[c] + depth * kk[c]   (0.5 folded in for tanh)
    float base[4], kk[4];
#pragma unroll
    for (int c = 0; c < 4; c++) {
        base[c] = 0.5f * (ox * __ldg(Wq + 0 * 4 + c) + oy * __ldg(Wq + 1 * 4 + c) + oz * __ldg(Wq + 2 * 4 + c)
                        + dx * __ldg(Wq + 3 * 4 + c) + dy * __ldg(Wq + 4 * 4 + c) + dz * __ldg(Wq + 5 * 4 + c));
        kk[c]   = 0.5f * (dx * __ldg(Wq + 0 * 4 + c) + dy * __ldg(Wq + 1 * 4 + c) + dz * __ldg(Wq + 2 * 4 + c));
    }

    float cdf[PTS];   // unnormalized cumsum of (w + 1e-5)

    // ---------------- Pass 1: coarse ray march + cdf build (early-exit) ----------------
    float absorption = 1.0f;
    float a0 = 0.0f, a1 = 0.0f, a2 = 0.0f;
    float cum = 0.0f;
    {
        int p = 0;
#pragma unroll 1
        for (; p < PTS; p++) {
            float d = NEARP + p * DSTEP;
            float op = sigm_h(fmaf(d, kk[0], base[0]));
            float v0 = sigm_h(fmaf(d, kk[1], base[1]));
            float v1 = sigm_h(fmaf(d, kk[2], base[2]));
            float v2 = sigm_h(fmaf(d, kk[3], base[3]));
            float w = op * absorption;
            absorption *= (1.0f - op);
            a0 = fmaf(w, v0, a0);
            a1 = fmaf(w, v1, a1);
            a2 = fmaf(w, v2, a2);
            cum += w + 1e-5f;
            cdf[p] = cum;
            if (__all_sync(0xffffffffu, absorption < EPS_ABS)) { p++; break; }
        }
        // tanh-free tail: w <= absorption < EPS -> increment is (w + 1e-5) ~= 1e-5
#pragma unroll 1
        for (; p < PTS; p++) {
            cum += 1e-5f;
            cdf[p] = cum;
        }
    }
    out[OFS_C + ((b * 3 + 0) << 16) + n] = a0;
    out[OFS_C + ((b * 3 + 1) << 16) + n] = a1;
    out[OFS_C + ((b * 3 + 2) << 16) + n] = a2;

    float inv_total = __fdividef(1.0f, cum);

    // ---------------- Fused pass 2+3: streaming CDF inversion inside the merge ----------------
    int   jp    = 0;
    float c_jm1 = 0.0f,  d_jm1 = NEARP;            // cdf_n[jp-1], depth[jp-1] (valid once jp>=1)
    float c_j   = cdf[0] * inv_total, d_j = NEARP; // cdf_n[jp],   depth[jp]
    float u     = 0.0f;                            // k/64, exact under incremental FADD

    auto gen_bin = [&]() -> float {
        while (jp < PTS && c_j <= u) {
            jp++;
            c_jm1 = c_j;  d_jm1 = d_j;
            if (jp < PTS) { c_j = cdf[jp] * inv_total; d_j += DSTEP; }
            else          { c_j = CUDART_INF_F; }
        }
        float c0 = (jp == 0)   ? c_j   : c_jm1;
        float d0 = (jp == 0)   ? d_j   : d_jm1;
        float c1 = (jp < PTS)  ? c_j   : c_jm1;
        float d1 = (jp < PTS)  ? d_j   : d_jm1;
        float dd = c1 - c0;
        float denom = (dd < 1e-8f) ? 1.0f : dd;
        float t = __fdividef(u - c0, denom);
        t = fminf(fmaxf(t, 0.0f), 1.0f);
        return fmaf(t, d1 - d0, d0);
    };

    float prev_bin = gen_bin();  u += (1.0f / 64.0f);   // bin_0 (== NEARP)
    float bin      = gen_bin();  u += (1.0f / 64.0f);   // bin_1
    float df = 0.5f * (prev_bin + bin);
    prev_bin = bin;
    int kf = 2;        // next bin index to generate
    int ic = 0;        // coarse points consumed
    float dc = NEARP;  // next coarse depth (incremental)

    absorption = 1.0f;
    a0 = a1 = a2 = 0.0f;
    float wsum = 0.0f, dsum = 0.0f;
#pragma unroll 1
    for (int m = 0; m < PTS + IMP; m++) {
        // remaining weights bounded by absorption -> residuals < 128*EPS, far below tolerance
        if (__all_sync(0xffffffffu, absorption < EPS_ABS)) break;
        bool take_c = (ic < PTS) && (dc <= df);    // df==+inf once fine exhausted
        float d = take_c ? dc : df;
        float op = sigm_h(fmaf(d, kk[0], base[0]));
        float v0 = sigm_h(fmaf(d, kk[1], base[1]));
        float v1 = sigm_h(fmaf(d, kk[2], base[2]));
        float v2 = sigm_h(fmaf(d, kk[3], base[3]));
        float w = op * absorption;
        absorption *= (1.0f - op);
        a0 = fmaf(w, v0, a0);
        a1 = fmaf(w, v1, a1);
        a2 = fmaf(w, v2, a2);
        wsum += w;
        dsum = fmaf(w, d, dsum);
        if (take_c) {
            ic++; dc += DSTEP;
        } else {
            if (kf <= IMP) {
                bin = gen_bin();  u += (1.0f / 64.0f);
                df = 0.5f * (prev_bin + bin);
                prev_bin = bin;
                kf++;
            } else {
                df = CUDART_INF_F;
            }
        }
    }
    out[OFS_F + ((b * 3 + 0) << 16) + n] = a0;
    out[OFS_F + ((b * 3 + 1) << 16) + n] = a1;
    out[OFS_F + ((b * 3 + 2) << 16) + n] = a2;

    // ray depth: sum(w*d) + (1 - clip(sum w,0,1)) * max(d_all) [= FAR exactly]
    float f_accum_op = fminf(wsum, 1.0f);
    float rd = dsum + (1.0f - f_accum_op) * FARP;

    // ---------------- global min/max + grid-wide barrier + normalize ----------------
    float mn = rd, mx = rd;
#pragma unroll
    for (int o = 16; o > 0; o >>= 1) {
        mn = fminf(mn, __shfl_xor_sync(0xffffffffu, mn, o));
        mx = fmaxf(mx, __shfl_xor_sync(0xffffffffu, mx, o));
    }
    if ((threadIdx.x & 31) == 0) {
        atomicMin(&g_min_bits, __float_as_int(mn));   // rd > 0: int order == float order
        atomicMax(&g_max_bits, __float_as_int(mx));
    }
    __syncthreads();

    // grid-wide barrier: whole grid is resident (launch_bounds guarantees it)
    if (threadIdx.x == 0) {
        __threadfence();
        int t = atomicAdd(&g_arrive, 1);
        if (t == NBLOCKS - 1) {
            g_arrive = 0;
            __threadfence();
            atomicExch(&g_release, 1);
        } else {
            while (atomicAdd(&g_release, 0) == 0) { __nanosleep(64); }
        }
        s_mn = __int_as_float(__ldcg(&g_min_bits));
        s_mx = __int_as_float(__ldcg(&g_max_bits));
    }
    __syncthreads();

    float inv = __fdividef(1.0f, s_mx - s_mn);
    out[OFS_D + (b << 16) + n] = (rd - s_mn) * inv;

    // reset state for the next graph replay (after every block has read min/max)
    __syncthreads();
    if (threadIdx.x == 0) {
        int t = atomicAdd(&g_done, 1);
        if (t == NBLOCKS - 1) {
            g_done     = 0;
            g_release  = 0;
            g_min_bits = 0x7f800000;
            g_max_bits = 0;
            __threadfence();
        }
    }
}

extern "C" void kernel_launch(void* const* d_in, const int* in_sizes, int n_in,
                              void* d_out, int out_size) {
    const float* tm = (const float*)d_in[0];   // transform_matrix (2,3,4)
    const float* Wq = (const float*)d_in[1];   // W_query (6,4)
    float* out = (float*)d_out;

    render_kernel<<<NBLOCKS, 128>>>(tm, Wq, out);
}